// round 1
// baseline (speedup 1.0000x reference)
#include <cuda_runtime.h>
#include <cuda_bf16.h>
#include <math.h>

// Problem constants
#define NN   4096
#define FF   128
#define HEADS 8
#define UU   8
#define CW   64            // HEADS*UU
#define BCOLS 80           // padded B/C width: 64 M-cols, 8 expR cols, 1 ones col, 7 pad

// GEMM tiling
#define BM 128
#define BK 16
#define KSPLIT 16
#define KCHUNK (NN / KSPLIT)   // 256

// Scratch (no allocations allowed)
__device__ float g_Bm[NN * BCOLS];                 // B matrix [4096 x 80]
__device__ float g_expEl[NN * HEADS];              // exp(e_l) [4096 x 8]
__device__ float g_Cp[(size_t)KSPLIT * NN * BCOLS];// split-K partials

// ---------------------------------------------------------------------------
// Kernel 1: prep. Computes HW = H@W per head, e_l/e_r, builds B matrix:
//   B[n][h*8+u]   = exp(e_r[h,n]) * HW[h,n,u]   (cols 0..63)
//   B[n][64+h]    = exp(e_r[h,n])               (cols 64..71)
//   B[n][72]      = 1.0  (degree column)
//   B[n][73..79]  = 0.0  (pad)
// Also stores exp(e_l[h,n]).
// Block: 256 threads, 8 nodes per block (2 passes of 4 nodes x 64 threads).
// ---------------------------------------------------------------------------
__global__ __launch_bounds__(256) void prep_kernel(
    const float* __restrict__ H, const float* __restrict__ W,
    const float* __restrict__ al, const float* __restrict__ ar)
{
    __shared__ float Ws[FF * CW];   // W permuted to [f][h*8+u], 32 KB
    __shared__ float Hs[4 * FF];    // 4 nodes
    __shared__ float HWs[4 * CW];
    __shared__ float elp[4 * CW];
    __shared__ float erp[4 * CW];
    __shared__ float eRs[4 * HEADS];

    int tid = threadIdx.x;

    // Load W permuted: Ws[f*64 + h*8 + u] = W[h*1024 + f*8 + u]
    #pragma unroll
    for (int i = 0; i < 32; i++) {
        int o = tid + i * 256;
        int f = o >> 6;
        int r = o & 63;
        int h = r >> 3, u = r & 7;
        Ws[o] = W[h * (FF * UU) + f * UU + u];
    }

    for (int pass = 0; pass < 2; pass++) {
        int nbase = blockIdx.x * 8 + pass * 4;
        __syncthreads();   // Ws ready (pass 0) / Hs reuse safe (pass 1)
        Hs[tid]       = H[(size_t)nbase * FF + tid];
        Hs[tid + 256] = H[(size_t)nbase * FF + tid + 256];
        __syncthreads();

        int g = tid >> 6;       // node within group of 4
        int t = tid & 63;       // (h,u) index
        int h = t >> 3, u = t & 7;

        float acc = 0.f;
        #pragma unroll 8
        for (int f = 0; f < FF; f++)
            acc += Hs[g * FF + f] * Ws[f * CW + t];

        HWs[tid] = acc;
        elp[tid] = acc * al[h * UU + u];
        erp[tid] = acc * ar[h * UU + u];
        __syncthreads();

        if (t < HEADS) {   // t = head index
            float el = 0.f, er = 0.f;
            #pragma unroll
            for (int u2 = 0; u2 < UU; u2++) {
                el += elp[g * CW + t * UU + u2];
                er += erp[g * CW + t * UU + u2];
            }
            eRs[g * HEADS + t] = expf(er);
            g_expEl[(size_t)(nbase + g) * HEADS + t] = expf(el);
        }
        __syncthreads();

        int n = nbase + g;
        g_Bm[(size_t)n * BCOLS + t] = HWs[tid] * eRs[g * HEADS + (t >> 3)];
        if (t < 16) {
            float v;
            if (t < 8)       v = eRs[g * HEADS + t];  // cols 64..71
            else if (t == 8) v = 1.0f;                // col 72 (degree)
            else             v = 0.0f;                // cols 73..79 pad
            g_Bm[(size_t)n * BCOLS + 64 + t] = v;
        }
    }
}

// ---------------------------------------------------------------------------
// Kernel 2: split-K fp32 GEMM. Cp[ks] += A[rows, kchunk] @ B[kchunk, 80]
// BM=128, BN=80, BK=16, 256 threads, thread tile 8x5. Deterministic
// (per-split partial slabs, no atomics).
// ---------------------------------------------------------------------------
__global__ __launch_bounds__(256) void gemm_kernel(const float* __restrict__ A)
{
    __shared__ float As[BK][132];   // transposed A tile, padded
    __shared__ float Bs[BK][BCOLS];

    int tid  = threadIdx.x;
    int row0 = blockIdx.x * BM;
    int ks   = blockIdx.y;
    int k0   = ks * KCHUNK;

    int tx = tid & 15;   // col group: cols tx*5 .. tx*5+4
    int ty = tid >> 4;   // row group: rows ty*8 .. ty*8+7

    float acc[8][5];
    #pragma unroll
    for (int i = 0; i < 8; i++)
        #pragma unroll
        for (int j = 0; j < 5; j++) acc[i][j] = 0.f;

    for (int kt = 0; kt < KCHUNK; kt += BK) {
        // Load A tile 128x16 (512 float4, 2 per thread), store transposed
        #pragma unroll
        for (int i = 0; i < 2; i++) {
            int idx = tid + i * 256;
            int r = idx >> 2;
            int c = (idx & 3) * 4;
            float4 v = *(const float4*)&A[(size_t)(row0 + r) * NN + k0 + kt + c];
            As[c + 0][r] = v.x; As[c + 1][r] = v.y;
            As[c + 2][r] = v.z; As[c + 3][r] = v.w;
        }
        // Load B tile 16x80 = 1280 floats (5 per thread, linear/coalesced)
        #pragma unroll
        for (int i = 0; i < 5; i++) {
            int idx = tid + i * 256;
            ((float*)Bs)[idx] = g_Bm[(size_t)(k0 + kt) * BCOLS + idx];
        }
        __syncthreads();

        #pragma unroll
        for (int kk = 0; kk < BK; kk++) {
            float4 a03 = *(const float4*)&As[kk][ty * 8];
            float4 a47 = *(const float4*)&As[kk][ty * 8 + 4];
            float a[8] = {a03.x, a03.y, a03.z, a03.w, a47.x, a47.y, a47.z, a47.w};
            float b[5];
            #pragma unroll
            for (int j = 0; j < 5; j++) b[j] = Bs[kk][tx * 5 + j];
            #pragma unroll
            for (int i = 0; i < 8; i++)
                #pragma unroll
                for (int j = 0; j < 5; j++)
                    acc[i][j] += a[i] * b[j];
        }
        __syncthreads();
    }

    float* out = g_Cp + (size_t)ks * NN * BCOLS;
    #pragma unroll
    for (int i = 0; i < 8; i++)
        #pragma unroll
        for (int j = 0; j < 5; j++)
            out[(size_t)(row0 + ty * 8 + i) * BCOLS + tx * 5 + j] = acc[i][j];
}

// ---------------------------------------------------------------------------
// Kernel 3: epilogue. Sum split-K partials, form denom, scale, ELU, write out.
//   denom[h,i] = (N - deg_i) + expEl[h,i] * S[h,i]
//   out[i, h*8+u] = elu(expEl[h,i] * T[h,i,u] / denom)
// ---------------------------------------------------------------------------
__global__ void epilogue_kernel(float* __restrict__ out)
{
    __shared__ float Crow[BCOLS];
    int i = blockIdx.x;
    int t = threadIdx.x;   // 80 threads

    float s = 0.f;
    #pragma unroll
    for (int ksp = 0; ksp < KSPLIT; ksp++)
        s += g_Cp[(size_t)ksp * NN * BCOLS + (size_t)i * BCOLS + t];
    Crow[t] = s;
    __syncthreads();

    if (t < CW) {
        int h = t >> 3;
        float T   = Crow[t];
        float S   = Crow[64 + h];
        float deg = Crow[72];
        float eEl = g_expEl[(size_t)i * HEADS + h];
        float denom = ((float)NN - deg) + eEl * S;
        float v = eEl * T / denom;
        out[(size_t)i * CW + t] = (v > 0.f) ? v : expm1f(v);
    }
}

// ---------------------------------------------------------------------------
extern "C" void kernel_launch(void* const* d_in, const int* in_sizes, int n_in,
                              void* d_out, int out_size)
{
    const float* A  = (const float*)d_in[0];   // [4096,4096]
    const float* H  = (const float*)d_in[1];   // [4096,128]
    const float* W  = (const float*)d_in[2];   // [8,128,8]
    const float* al = (const float*)d_in[3];   // [8,8]
    const float* ar = (const float*)d_in[4];   // [8,8]
    float* out = (float*)d_out;                // [4096,64]

    prep_kernel<<<NN / 8, 256>>>(H, W, al, ar);
    gemm_kernel<<<dim3(NN / BM, KSPLIT), 256>>>(A);
    epilogue_kernel<<<NN, BCOLS>>>(out);
}

// round 4
// speedup vs baseline: 1.6316x; 1.6316x over previous
#include <cuda_runtime.h>
#include <cuda_bf16.h>
#include <math.h>

// Problem constants
#define NN    4096
#define FF    128
#define HEADS 8
#define UU    8
#define CW    64           // HEADS*UU
#define BCOLS 80           // 64 M-cols, 8 expR cols, 1 ones col, 7 pad

// GEMM tiling
#define BM 128
#define BK 32
#define KSPLIT 16
#define KCHUNK (NN / KSPLIT)   // 256

// Scratch (no allocations allowed)
// B stored n-major: g_B*[c][k] for easy B-fragment loads (col-major frags).
__device__ __nv_bfloat16 g_Bh[(size_t)BCOLS * NN];
__device__ __nv_bfloat16 g_Bl[(size_t)BCOLS * NN];
__device__ float g_expEl[NN * HEADS];
__device__ float g_Cp[(size_t)KSPLIT * NN * BCOLS];   // split-K partials

// ---------------------------------------------------------------------------
// Kernel 1: prep. HW = H@W per head, e_l/e_r, build split-bf16 B (transposed):
//   row c = h*8+u (c<64):  B[c][n] = exp(e_r[h,n]) * HW[h,n,u]
//   row 64+h:              B[..][n] = exp(e_r[h,n])
//   row 72:                1.0 (degree column);  rows 73..79: 0
// hi/lo split: b_hi = bf16(v), b_lo = bf16(v - b_hi).
// 256 blocks x 256 threads, 16 nodes/block (4 passes of 4 nodes x 64 thr).
// ---------------------------------------------------------------------------
__global__ __launch_bounds__(256) void prep_kernel(
    const float* __restrict__ H, const float* __restrict__ W,
    const float* __restrict__ al, const float* __restrict__ ar)
{
    __shared__ float Ws[FF * CW];   // W permuted to [f][h*8+u], 32 KB
    __shared__ float Hs[4 * FF];
    __shared__ float HWs[4 * CW];
    __shared__ float elp[4 * CW];
    __shared__ float erp[4 * CW];
    __shared__ float eRs[4 * HEADS];

    int tid = threadIdx.x;

    // Ws[f*64 + h*8 + u] = W[h*1024 + f*8 + u]
    #pragma unroll
    for (int i = 0; i < 32; i++) {
        int o = tid + i * 256;
        int f = o >> 6;
        int r = o & 63;
        int h = r >> 3, u = r & 7;
        Ws[o] = W[h * (FF * UU) + f * UU + u];
    }

    for (int pass = 0; pass < 4; pass++) {
        int nbase = blockIdx.x * 16 + pass * 4;
        __syncthreads();
        Hs[tid]       = H[(size_t)nbase * FF + tid];
        Hs[tid + 256] = H[(size_t)nbase * FF + tid + 256];
        __syncthreads();

        int g = tid >> 6;       // node within group of 4
        int t = tid & 63;       // (h,u) index
        int h = t >> 3, u = t & 7;

        float acc = 0.f;
        #pragma unroll 8
        for (int f = 0; f < FF; f++)
            acc += Hs[g * FF + f] * Ws[f * CW + t];

        HWs[tid] = acc;
        elp[tid] = acc * al[h * UU + u];
        erp[tid] = acc * ar[h * UU + u];
        __syncthreads();

        if (t < HEADS) {   // t = head
            float el = 0.f, er = 0.f;
            #pragma unroll
            for (int u2 = 0; u2 < UU; u2++) {
                el += elp[g * CW + t * UU + u2];
                er += erp[g * CW + t * UU + u2];
            }
            eRs[g * HEADS + t] = expf(er);
            g_expEl[(size_t)(nbase + g) * HEADS + t] = expf(el);
        }
        __syncthreads();

        int n = nbase + g;
        float v = HWs[tid] * eRs[g * HEADS + h];
        __nv_bfloat16 bh = __float2bfloat16(v);
        g_Bh[(size_t)t * NN + n] = bh;
        g_Bl[(size_t)t * NN + n] = __float2bfloat16(v - __bfloat162float(bh));
        if (t < 16) {
            float v2 = (t < 8) ? eRs[g * HEADS + t] : ((t == 8) ? 1.0f : 0.0f);
            __nv_bfloat16 bh2 = __float2bfloat16(v2);
            g_Bh[(size_t)(64 + t) * NN + n] = bh2;
            g_Bl[(size_t)(64 + t) * NN + n] =
                __float2bfloat16(v2 - __bfloat162float(bh2));
        }
    }
}

// ---------------------------------------------------------------------------
// Kernel 2: split-K tensor-core GEMM. Cp[ks] = A[rows, kchunk] @ (Bh + Bl).
// A (fp32, exact 0/1) converted to bf16 in-flight. mma.sync.m16n8k16 bf16,
// fp32 accum. 256 threads = 8 warps in 4x2 grid; warp tile 32x40.
// ---------------------------------------------------------------------------
#define MMA16816(d, a, b0, b1)                                              \
    asm volatile(                                                           \
        "mma.sync.aligned.m16n8k16.row.col.f32.bf16.bf16.f32 "              \
        "{%0,%1,%2,%3}, {%4,%5,%6,%7}, {%8,%9}, {%0,%1,%2,%3};"             \
        : "+f"(d[0]), "+f"(d[1]), "+f"(d[2]), "+f"(d[3])                    \
        : "r"(a[0]), "r"(a[1]), "r"(a[2]), "r"(a[3]), "r"(b0), "r"(b1))

__global__ __launch_bounds__(256) void gemm_kernel(const float* __restrict__ A)
{
    __shared__ __nv_bfloat16 As[BM][BK + 2];     // 128 x 34
    __shared__ __nv_bfloat16 Bhs[BCOLS][BK + 2]; // 80 x 34 (n-major)
    __shared__ __nv_bfloat16 Bls[BCOLS][BK + 2];

    int tid  = threadIdx.x;
    int lane = tid & 31;
    int warp = tid >> 5;
    int wr = warp & 3;    // warp row -> rows wr*32 .. +31
    int wc = warp >> 2;   // warp col -> cols wc*40 .. +39
    int row0 = blockIdx.x * BM;
    int ks   = blockIdx.y;
    int k0   = ks * KCHUNK;

    float acc[2][5][4];
    #pragma unroll
    for (int m = 0; m < 2; m++)
        #pragma unroll
        for (int j = 0; j < 5; j++)
            #pragma unroll
            for (int q = 0; q < 4; q++) acc[m][j][q] = 0.f;

    for (int kt = 0; kt < KCHUNK; kt += BK) {
        // A tile 128x32 fp32 -> bf16 smem (1024 float4, 4 per thread)
        #pragma unroll
        for (int i = 0; i < 4; i++) {
            int idx = tid + i * 256;
            int r  = idx >> 3;          // 8 float4 per row
            int c4 = (idx & 7) * 4;
            float4 v = *(const float4*)&A[(size_t)(row0 + r) * NN + k0 + kt + c4];
            *(__nv_bfloat162*)&As[r][c4]     = __floats2bfloat162_rn(v.x, v.y);
            *(__nv_bfloat162*)&As[r][c4 + 2] = __floats2bfloat162_rn(v.z, v.w);
        }
        // B tiles: 80 x 32 bf16 each = 1280 bf16x2, 5 per thread per matrix
        #pragma unroll
        for (int i = 0; i < 5; i++) {
            int e  = tid + i * 256;     // 0..1279
            int c  = e >> 4;            // 16 bf16x2 per row
            int kk = e & 15;
            __nv_bfloat162 vh =
                ((const __nv_bfloat162*)(g_Bh + (size_t)c * NN + k0 + kt))[kk];
            __nv_bfloat162 vl =
                ((const __nv_bfloat162*)(g_Bl + (size_t)c * NN + k0 + kt))[kk];
            *(__nv_bfloat162*)&Bhs[c][kk * 2] = vh;
            *(__nv_bfloat162*)&Bls[c][kk * 2] = vl;
        }
        __syncthreads();

        #pragma unroll
        for (int kb = 0; kb < BK; kb += 16) {
            unsigned a[2][4];
            int ar0 = wr * 32 + (lane >> 2);
            int ac  = (lane & 3) * 2 + kb;
            #pragma unroll
            for (int m = 0; m < 2; m++) {
                int r = ar0 + m * 16;
                a[m][0] = *(const unsigned*)&As[r][ac];
                a[m][1] = *(const unsigned*)&As[r + 8][ac];
                a[m][2] = *(const unsigned*)&As[r][ac + 8];
                a[m][3] = *(const unsigned*)&As[r + 8][ac + 8];
            }
            #pragma unroll
            for (int j = 0; j < 5; j++) {
                int n  = wc * 40 + j * 8 + (lane >> 2);
                int kr = (lane & 3) * 2 + kb;
                unsigned bh0 = *(const unsigned*)&Bhs[n][kr];
                unsigned bh1 = *(const unsigned*)&Bhs[n][kr + 8];
                unsigned bl0 = *(const unsigned*)&Bls[n][kr];
                unsigned bl1 = *(const unsigned*)&Bls[n][kr + 8];
                #pragma unroll
                for (int m = 0; m < 2; m++) {
                    MMA16816(acc[m][j], a[m], bh0, bh1);
                    MMA16816(acc[m][j], a[m], bl0, bl1);
                }
            }
        }
        __syncthreads();
    }

    float* out = g_Cp + (size_t)ks * NN * BCOLS;
    #pragma unroll
    for (int m = 0; m < 2; m++)
        #pragma unroll
        for (int j = 0; j < 5; j++) {
            int r = row0 + wr * 32 + m * 16 + (lane >> 2);
            int c = wc * 40 + j * 8 + (lane & 3) * 2;
            out[(size_t)r * BCOLS + c]           = acc[m][j][0];
            out[(size_t)r * BCOLS + c + 1]       = acc[m][j][1];
            out[(size_t)(r + 8) * BCOLS + c]     = acc[m][j][2];
            out[(size_t)(r + 8) * BCOLS + c + 1] = acc[m][j][3];
        }
}

// ---------------------------------------------------------------------------
// Kernel 3: epilogue. Sum split-K partials, form denom, scale, ELU, write.
//   denom[h,i] = (N - deg_i) + expEl[h,i] * S[h,i]
//   out[i, h*8+u] = elu(expEl[h,i] * T[h,i,u] / denom)
// ---------------------------------------------------------------------------
__global__ void epilogue_kernel(float* __restrict__ out)
{
    __shared__ float Crow[BCOLS];
    int i = blockIdx.x;
    int t = threadIdx.x;   // 80 threads

    float s = 0.f;
    #pragma unroll
    for (int ksp = 0; ksp < KSPLIT; ksp++)
        s += g_Cp[(size_t)ksp * NN * BCOLS + (size_t)i * BCOLS + t];
    Crow[t] = s;
    __syncthreads();

    if (t < CW) {
        int h = t >> 3;
        float T   = Crow[t];
        float S   = Crow[64 + h];
        float deg = Crow[72];
        float eEl = g_expEl[(size_t)i * HEADS + h];
        float denom = ((float)NN - deg) + eEl * S;
        float v = eEl * T / denom;
        out[(size_t)i * CW + t] = (v > 0.f) ? v : expm1f(v);
    }
}

// ---------------------------------------------------------------------------
extern "C" void kernel_launch(void* const* d_in, const int* in_sizes, int n_in,
                              void* d_out, int out_size)
{
    const float* A  = (const float*)d_in[0];   // [4096,4096]
    const float* H  = (const float*)d_in[1];   // [4096,128]
    const float* W  = (const float*)d_in[2];   // [8,128,8]
    const float* al = (const float*)d_in[3];   // [8,8]
    const float* ar = (const float*)d_in[4];   // [8,8]
    float* out = (float*)d_out;                // [4096,64]

    prep_kernel<<<256, 256>>>(H, W, al, ar);
    gemm_kernel<<<dim3(NN / BM, KSPLIT), 256>>>(A);
    epilogue_kernel<<<NN, BCOLS>>>(out);
}

// round 8
// speedup vs baseline: 1.8778x; 1.1509x over previous
#include <cuda_runtime.h>
#include <cuda_bf16.h>
#include <math.h>

// Problem constants
#define NN    4096
#define FF    128
#define HEADS 8
#define UU    8
#define CW    64           // HEADS*UU
#define BCOLS 80           // 64 M-cols, 8 expR cols, 1 ones col, 7 pad

// GEMM tiling
#define BM 128
#define BK 32
#define KSPLIT 16
#define KCHUNK (NN / KSPLIT)   // 256
#define NT (KCHUNK / BK)       // 8 tiles per CTA

// Scratch (no allocations allowed)
__device__ float          g_Wp[CW * FF];                 // W transposed [t][f]
__device__ __nv_bfloat16  g_Bh[(size_t)NN * BCOLS];      // B hi, n-major [node][80]
__device__ __nv_bfloat16  g_Bl[(size_t)NN * BCOLS];      // B lo
__device__ float          g_expEl[NN * HEADS];
__device__ float          g_Cp[(size_t)KSPLIT * NN * BCOLS];  // split-K partials

// ---------------------------------------------------------------------------
// Kernel 0: transpose W -> Wp[t][f], t = h*8+u
// ---------------------------------------------------------------------------
__global__ void wt_kernel(const float* __restrict__ W)
{
    int o = blockIdx.x * 256 + threadIdx.x;   // 0..8191
    int t = o >> 7, f = o & 127;
    g_Wp[o] = W[(t >> 3) * (FF * UU) + f * UU + (t & 7)];
}

// ---------------------------------------------------------------------------
// Kernel 1: prep. Warp-per-node: H row in regs, Wp in smem, butterfly reduce.
// Builds split-bf16 B (n-major): B[n][c], c<64: exp(e_r)*HW; 64+h: exp(e_r);
// 72: 1.0 (degree col); 73..79: 0.  Also exp(e_l) per (n,h).
// 256 blocks x 256 threads (8 warps), 2 nodes per warp.
// ---------------------------------------------------------------------------
__global__ __launch_bounds__(256) void prep_kernel(
    const float* __restrict__ H,
    const float* __restrict__ al_g, const float* __restrict__ ar_g)
{
    __shared__ float Ws[CW * FF];   // 32 KB, [t][f]

    int tid = threadIdx.x, lane = tid & 31, warp = tid >> 5;

    #pragma unroll
    for (int i = 0; i < 8; i++)
        ((float4*)Ws)[tid + i * 256] = ((const float4*)g_Wp)[tid + i * 256];

    float al0 = __ldg(al_g + lane),      ar0 = __ldg(ar_g + lane);
    float al1 = __ldg(al_g + 32 + lane), ar1 = __ldg(ar_g + 32 + lane);
    __syncthreads();

    #pragma unroll
    for (int rep = 0; rep < 2; rep++) {
        int n = blockIdx.x * 16 + warp * 2 + rep;
        float4 h4 = *(const float4*)&H[(size_t)n * FF + lane * 4];

        float hw0 = 0.f, hw1 = 0.f;
        #pragma unroll
        for (int t = 0; t < 64; t++) {
            float4 w4 = *(const float4*)&Ws[t * FF + lane * 4];
            float p = h4.x * w4.x + h4.y * w4.y + h4.z * w4.z + h4.w * w4.w;
            #pragma unroll
            for (int m = 16; m; m >>= 1)
                p += __shfl_xor_sync(0xffffffffu, p, m);
            if ((t & 31) == lane) { if (t < 32) hw0 = p; else hw1 = p; }
        }

        float el0 = hw0 * al0, er0 = hw0 * ar0;
        float el1 = hw1 * al1, er1 = hw1 * ar1;
        #pragma unroll
        for (int m = 1; m < 8; m <<= 1) {
            el0 += __shfl_xor_sync(0xffffffffu, el0, m);
            er0 += __shfl_xor_sync(0xffffffffu, er0, m);
            el1 += __shfl_xor_sync(0xffffffffu, el1, m);
            er1 += __shfl_xor_sync(0xffffffffu, er1, m);
        }
        float eR0 = expf(er0), eR1 = expf(er1);
        if ((lane & 7) == 0) {
            g_expEl[n * HEADS + (lane >> 3)]     = expf(el0);
            g_expEl[n * HEADS + 4 + (lane >> 3)] = expf(el1);
        }
        float v0 = hw0 * eR0, v1 = hw1 * eR1;
        __nv_bfloat16 b0 = __float2bfloat16(v0);
        __nv_bfloat16 b1 = __float2bfloat16(v1);
        g_Bh[(size_t)n * BCOLS + lane]      = b0;
        g_Bl[(size_t)n * BCOLS + lane]      = __float2bfloat16(v0 - __bfloat162float(b0));
        g_Bh[(size_t)n * BCOLS + 32 + lane] = b1;
        g_Bl[(size_t)n * BCOLS + 32 + lane] = __float2bfloat16(v1 - __bfloat162float(b1));

        // cols 64..79: head eRs, degree-1, pad zeros
        float eRlo = __shfl_sync(0xffffffffu, eR0, (lane & 3) * 8);
        float eRhi = __shfl_sync(0xffffffffu, eR1, (lane & 3) * 8);
        if (lane < 16) {
            float v2 = (lane < 4) ? eRlo
                     : (lane < 8) ? eRhi
                     : (lane == 8) ? 1.0f : 0.0f;
            __nv_bfloat16 b2 = __float2bfloat16(v2);
            g_Bh[(size_t)n * BCOLS + 64 + lane] = b2;
            g_Bl[(size_t)n * BCOLS + 64 + lane] =
                __float2bfloat16(v2 - __bfloat162float(b2));
        }
    }
}

// ---------------------------------------------------------------------------
// Kernel 2: pipelined split-K tensor-core GEMM. Cp[ks] = A @ (Bh + Bl).
// A fp32 (exact 0/1) LDG->cvt->STS; B bf16 via cp.async double-buffer.
// ldmatrix for all fragments. 256 threads = 8 warps (4 row x 2 col).
// ---------------------------------------------------------------------------
#define MMA16816(d, a, b0v, b1v)                                            \
    asm volatile(                                                           \
        "mma.sync.aligned.m16n8k16.row.col.f32.bf16.bf16.f32 "              \
        "{%0,%1,%2,%3}, {%4,%5,%6,%7}, {%8,%9}, {%0,%1,%2,%3};"             \
        : "+f"(d[0]), "+f"(d[1]), "+f"(d[2]), "+f"(d[3])                    \
        : "r"(a[0]), "r"(a[1]), "r"(a[2]), "r"(a[3]), "r"(b0v), "r"(b1v))

#define LDSM_X4(r0, r1, r2, r3, addr)                                       \
    asm volatile("ldmatrix.sync.aligned.m8n8.x4.shared.b16 "                \
                 "{%0,%1,%2,%3}, [%4];"                                     \
                 : "=r"(r0), "=r"(r1), "=r"(r2), "=r"(r3) : "r"(addr))

#define LDSM_X4T(r0, r1, r2, r3, addr)                                      \
    asm volatile("ldmatrix.sync.aligned.m8n8.x4.trans.shared.b16 "          \
                 "{%0,%1,%2,%3}, [%4];"                                     \
                 : "=r"(r0), "=r"(r1), "=r"(r2), "=r"(r3) : "r"(addr))

#define LDSM_X2T(r0, r1, addr)                                              \
    asm volatile("ldmatrix.sync.aligned.m8n8.x2.trans.shared.b16 "          \
                 "{%0,%1}, [%2];"                                           \
                 : "=r"(r0), "=r"(r1) : "r"(addr))

#define CP_ASYNC16(smaddr, gptr)                                            \
    asm volatile("cp.async.cg.shared.global [%0], [%1], 16;"                \
                 :: "r"(smaddr), "l"(gptr))

__global__ __launch_bounds__(256) void gemm_kernel(const float* __restrict__ A)
{
    __shared__ __nv_bfloat16 As[2][BM][40];     // 20 KB
    __shared__ __nv_bfloat16 Bhs[2][BK][88];    // 11 KB
    __shared__ __nv_bfloat16 Bls[2][BK][88];    // 11 KB

    int tid  = threadIdx.x;
    int lane = tid & 31;
    int warp = tid >> 5;
    int wr = warp & 3;          // rows wr*32..+31
    int wc = warp >> 2;         // cols wc*40..+39
    int row0 = blockIdx.x * BM;
    int k0   = blockIdx.y * KCHUNK;

    float acc[2][5][4];
    #pragma unroll
    for (int m = 0; m < 2; m++)
        #pragma unroll
        for (int j = 0; j < 5; j++)
            #pragma unroll
            for (int q = 0; q < 4; q++) acc[m][j][q] = 0.f;

    const float* aptr =
        A + (size_t)(row0 + (tid >> 1)) * NN + k0 + (tid & 1) * 16;

    float4 av[4];

    // ---- prologue: tile 0 ----
    #pragma unroll
    for (int q = 0; q < 4; q++) av[q] = *(const float4*)(aptr + q * 4);
    #pragma unroll
    for (int i = 0; i < 3; i++) {
        int c = tid + i * 256;
        if (c < 640) {
            int mat = c >= 320;
            int cc  = mat ? c - 320 : c;
            int kr = cc / 10, ch = cc % 10;
            const __nv_bfloat16* src =
                (mat ? g_Bl : g_Bh) + (size_t)(k0 + kr) * BCOLS + ch * 8;
            unsigned d = (unsigned)__cvta_generic_to_shared(
                mat ? &Bls[0][kr][ch * 8] : &Bhs[0][kr][ch * 8]);
            CP_ASYNC16(d, src);
        }
    }
    asm volatile("cp.async.commit_group;");

    for (int kt = 0; kt < NT; kt++) {
        int buf = kt & 1;

        // STS A (convert fp32 -> bf16)
        {
            unsigned r8[8];
            #pragma unroll
            for (int q = 0; q < 4; q++) {
                __nv_bfloat162 p0 = __floats2bfloat162_rn(av[q].x, av[q].y);
                __nv_bfloat162 p1 = __floats2bfloat162_rn(av[q].z, av[q].w);
                r8[q * 2]     = *(unsigned*)&p0;
                r8[q * 2 + 1] = *(unsigned*)&p1;
            }
            __nv_bfloat16* dst = &As[buf][tid >> 1][(tid & 1) * 16];
            *(uint4*)dst       = make_uint4(r8[0], r8[1], r8[2], r8[3]);
            *(uint4*)(dst + 8) = make_uint4(r8[4], r8[5], r8[6], r8[7]);
        }

        // issue next tile loads
        if (kt + 1 < NT) {
            #pragma unroll
            for (int q = 0; q < 4; q++)
                av[q] = *(const float4*)(aptr + (kt + 1) * BK + q * 4);
            #pragma unroll
            for (int i = 0; i < 3; i++) {
                int c = tid + i * 256;
                if (c < 640) {
                    int mat = c >= 320;
                    int cc  = mat ? c - 320 : c;
                    int kr = cc / 10, ch = cc % 10;
                    const __nv_bfloat16* src = (mat ? g_Bl : g_Bh) +
                        (size_t)(k0 + (kt + 1) * BK + kr) * BCOLS + ch * 8;
                    unsigned d = (unsigned)__cvta_generic_to_shared(
                        mat ? &Bls[buf ^ 1][kr][ch * 8]
                            : &Bhs[buf ^ 1][kr][ch * 8]);
                    CP_ASYNC16(d, src);
                }
            }
            asm volatile("cp.async.commit_group;");
            asm volatile("cp.async.wait_group 1;");
        } else {
            asm volatile("cp.async.commit_group;");
            asm volatile("cp.async.wait_group 0;");
        }
        __syncthreads();

        // ---- compute tile ----
        unsigned aBase = (unsigned)__cvta_generic_to_shared(&As[buf][0][0]);
        #pragma unroll
        for (int kb = 0; kb < BK; kb += 16) {
            unsigned a[2][4];
            int lr = lane & 15, lc = lane >> 4;
            #pragma unroll
            for (int m = 0; m < 2; m++) {
                unsigned ad = aBase +
                    ((wr * 32 + m * 16 + lr) * 40 + kb + lc * 8) * 2;
                LDSM_X4(a[m][0], a[m][1], a[m][2], a[m][3], ad);
            }

            unsigned bh[5][2], bl[5][2];
            {
                int mm = lane >> 3;                       // 0..3
                int krow = kb + (mm & 1) * 8 + (lane & 7);
                #pragma unroll
                for (int jj = 0; jj < 2; jj++) {
                    int ncol = wc * 40 + jj * 16 + (mm >> 1) * 8;
                    unsigned adh = (unsigned)__cvta_generic_to_shared(
                        &Bhs[buf][krow][ncol]);
                    LDSM_X4T(bh[jj * 2][0], bh[jj * 2][1],
                             bh[jj * 2 + 1][0], bh[jj * 2 + 1][1], adh);
                    unsigned adl = (unsigned)__cvta_generic_to_shared(
                        &Bls[buf][krow][ncol]);
                    LDSM_X4T(bl[jj * 2][0], bl[jj * 2][1],
                             bl[jj * 2 + 1][0], bl[jj * 2 + 1][1], adl);
                }
                int krow2 = kb + ((lane >> 3) & 1) * 8 + (lane & 7);
                unsigned ad2h = (unsigned)__cvta_generic_to_shared(
                    &Bhs[buf][krow2][wc * 40 + 32]);
                LDSM_X2T(bh[4][0], bh[4][1], ad2h);
                unsigned ad2l = (unsigned)__cvta_generic_to_shared(
                    &Bls[buf][krow2][wc * 40 + 32]);
                LDSM_X2T(bl[4][0], bl[4][1], ad2l);
            }

            #pragma unroll
            for (int j = 0; j < 5; j++)
                #pragma unroll
                for (int m = 0; m < 2; m++) {
                    MMA16816(acc[m][j], a[m], bh[j][0], bh[j][1]);
                    MMA16816(acc[m][j], a[m], bl[j][0], bl[j][1]);
                }
        }
        // no trailing sync needed: next iter writes the other buffers, and
        // the sync at the top of iter kt+1 orders reuse two tiles ahead.
        __syncthreads();
    }

    float* out = g_Cp + (size_t)blockIdx.y * NN * BCOLS;
    #pragma unroll
    for (int m = 0; m < 2; m++)
        #pragma unroll
        for (int j = 0; j < 5; j++) {
            int r = row0 + wr * 32 + m * 16 + (lane >> 2);
            int c = wc * 40 + j * 8 + (lane & 3) * 2;
            out[(size_t)r * BCOLS + c]           = acc[m][j][0];
            out[(size_t)r * BCOLS + c + 1]       = acc[m][j][1];
            out[(size_t)(r + 8) * BCOLS + c]     = acc[m][j][2];
            out[(size_t)(r + 8) * BCOLS + c + 1] = acc[m][j][3];
        }
}

// ---------------------------------------------------------------------------
// Kernel 3: epilogue. Sum split-K partials, denom, scale, ELU, write.
//   denom[h,i] = (N - deg_i) + expEl[h,i] * S[h,i]
//   out[i, h*8+u] = elu(expEl[h,i] * T[h,i,u] / denom)
// ---------------------------------------------------------------------------
__global__ void epilogue_kernel(float* __restrict__ out)
{
    __shared__ float Crow[BCOLS];
    int i = blockIdx.x;
    int t = threadIdx.x;   // 80 threads

    float s = 0.f;
    #pragma unroll
    for (int ksp = 0; ksp < KSPLIT; ksp++)
        s += g_Cp[(size_t)ksp * NN * BCOLS + (size_t)i * BCOLS + t];
    Crow[t] = s;
    __syncthreads();

    if (t < CW) {
        int h = t >> 3;
        float T   = Crow[t];
        float S   = Crow[64 + h];
        float deg = Crow[72];
        float eEl = g_expEl[(size_t)i * HEADS + h];
        float denom = ((float)NN - deg) + eEl * S;
        float v = eEl * T / denom;
        out[(size_t)i * CW + t] = (v > 0.f) ? v : expm1f(v);
    }
}

// ---------------------------------------------------------------------------
extern "C" void kernel_launch(void* const* d_in, const int* in_sizes, int n_in,
                              void* d_out, int out_size)
{
    const float* A  = (const float*)d_in[0];   // [4096,4096]
    const float* H  = (const float*)d_in[1];   // [4096,128]
    const float* W  = (const float*)d_in[2];   // [8,128,8]
    const float* al = (const float*)d_in[3];   // [8,8]
    const float* ar = (const float*)d_in[4];   // [8,8]
    float* out = (float*)d_out;                // [4096,64]

    wt_kernel<<<32, 256>>>(W);
    prep_kernel<<<256, 256>>>(H, al, ar);
    gemm_kernel<<<dim3(NN / BM, KSPLIT), 256>>>(A);
    epilogue_kernel<<<NN, BCOLS>>>(out);
}